// round 2
// baseline (speedup 1.0000x reference)
#include <cuda_runtime.h>

// Problem constants (Correlation1dCost): feat [B,C,H,W] f32, out [B,D,H,W] f32
#define B_ 8
#define C_ 128
#define H_ 128
#define W_ 256
#define D_ 48
#define PAD_ 47

// Tiling
#define XT 128           // x-tile per block
#define CK 16            // channels per smem chunk
#define S2W (XT + PAD_)  // 175 feat2 window width
#define S2P 176          // padded row (keeps float2 alignment, bounds)

__device__ __forceinline__ float lrelu(float v) {
    return v >= 0.0f ? v : 0.1f * v;
}

__global__ __launch_bounds__(128)
void corr1d_kernel(const float* __restrict__ f1,
                   const float* __restrict__ f2,
                   float* __restrict__ out) {
    __shared__ float s1[CK][XT];
    __shared__ float s2[CK][S2P];

    const int tid = threadIdx.x;
    const int x0  = blockIdx.x * XT;       // 0 or 128
    const int by  = blockIdx.y;            // b*H + y
    const int b   = by / H_;
    const int y   = by % H_;

    // thread tile: tx in [0,16) over x (8 each), td in [0,8) over d (6 each)
    // td fastest within warp -> feat1 float4 loads broadcast across td,
    // feat2 float2 loads have low bank-conflict degree.
    const int tx = tid >> 3;
    const int td = tid & 7;
    const int xb = tx * 8;   // x offset within tile
    const int db = td * 6;   // d offset

    float acc[8][6];
#pragma unroll
    for (int i = 0; i < 8; ++i)
#pragma unroll
        for (int j = 0; j < 6; ++j) acc[i][j] = 0.0f;

    const int HW = H_ * W_;
    const float* f1row = f1 + (b * C_ * H_ + y) * W_ + x0;  // + c*HW + xx
    const float* f2row = f2 + (b * C_ * H_ + y) * W_;       // + c*HW + gx

    for (int c0 = 0; c0 < C_; c0 += CK) {
        __syncthreads();
        // ---- load feat1 tile: CK x 128, one float per thread per channel
#pragma unroll
        for (int c = 0; c < CK; ++c) {
            s1[c][tid] = f1row[(c0 + c) * HW + tid];
        }
        // ---- load feat2 window: CK x 175 (zero-pad left OOB)
#pragma unroll
        for (int c = 0; c < CK; ++c) {
            const float* p = f2row + (c0 + c) * HW;
            {
                int gx = x0 - PAD_ + tid;            // tid in [0,128)
                s2[c][tid] = (gx >= 0) ? p[gx] : 0.0f;
            }
            int k2 = tid + 128;
            if (k2 < S2W) {
                int gx = x0 - PAD_ + k2;             // always in [81,255]
                s2[c][k2] = p[gx];
            }
        }
        __syncthreads();

        // ---- compute
#pragma unroll
        for (int c = 0; c < CK; ++c) {
            float a[8];
            float4 a0 = *reinterpret_cast<const float4*>(&s1[c][xb]);
            float4 a1 = *reinterpret_cast<const float4*>(&s1[c][xb + 4]);
            a[0] = a0.x; a[1] = a0.y; a[2] = a0.z; a[3] = a0.w;
            a[4] = a1.x; a[5] = a1.y; a[6] = a1.z; a[7] = a1.w;

            // feat2 window for this thread: s2[c][xb+db .. xb+db+12]
            float bw[14];
            const float* bp = &s2[c][xb + db];       // xb+db is even -> float2 ok
#pragma unroll
            for (int k = 0; k < 7; ++k) {
                float2 v = *reinterpret_cast<const float2*>(bp + 2 * k);
                bw[2 * k]     = v.x;
                bw[2 * k + 1] = v.y;
            }

#pragma unroll
            for (int i = 0; i < 8; ++i)
#pragma unroll
                for (int j = 0; j < 6; ++j)
                    acc[i][j] = fmaf(a[i], bw[i + j], acc[i][j]);
        }
    }

    // ---- store: per d, 8 contiguous x as two float4 (fully coalesced)
#pragma unroll
    for (int j = 0; j < 6; ++j) {
        const int d = db + j;
        float* op = out + ((b * D_ + d) * H_ + y) * W_ + x0 + xb;
        float4 v0, v1;
        v0.x = lrelu(acc[0][j]); v0.y = lrelu(acc[1][j]);
        v0.z = lrelu(acc[2][j]); v0.w = lrelu(acc[3][j]);
        v1.x = lrelu(acc[4][j]); v1.y = lrelu(acc[5][j]);
        v1.z = lrelu(acc[6][j]); v1.w = lrelu(acc[7][j]);
        *reinterpret_cast<float4*>(op)     = v0;
        *reinterpret_cast<float4*>(op + 4) = v1;
    }
}

extern "C" void kernel_launch(void* const* d_in, const int* in_sizes, int n_in,
                              void* d_out, int out_size) {
    (void)in_sizes; (void)n_in; (void)out_size;
    const float* f1 = (const float*)d_in[0];
    const float* f2 = (const float*)d_in[1];
    float* out = (float*)d_out;

    dim3 grid(W_ / XT, B_ * H_);
    corr1d_kernel<<<grid, 128>>>(f1, f2, out);
}